// round 16
// baseline (speedup 1.0000x reference)
#include <cuda_runtime.h>
#include <cuda_fp16.h>
#include <math.h>
#include <stdint.h>

#define Bx 16
#define Sx 384
#define Hx 768
#define ESSx 6
#define HEADERx 9
#define Px 73920
#define Mx (Bx*Sx)
#define SSx ((long)Sx*Sx)

__device__ float g_cos[Sx*32];
__device__ float g_sin[Sx*32];
__device__ __align__(16) float g_lin[Mx*128];
__device__ __align__(16) float g_lin2[2*Mx*576];
__device__ __align__(16) float g_scg[(size_t)Bx*HEADERx*Sx*Sx];
__device__ __align__(16) float g_stg[(size_t)Bx*Sx*Sx];
__device__ __align__(16) float g_stp[(size_t)Bx*Sx*Sx];
__device__ __align__(16) float g_sp [(size_t)Bx*ESSx*Sx*Sx];
__device__ __align__(16) float g_agg[Mx*Hx];

__device__ __align__(16) uint32_t g_xh[Mx*384], g_xl[Mx*384];
__device__ __align__(16) uint32_t g_hidh[Mx*960], g_hidl[Mx*960];
__device__ __align__(16) uint32_t g_tsqh[Mx*32], g_tsql[Mx*32], g_tskh[Mx*32], g_tskl[Mx*32];
__device__ __align__(16) uint32_t g_tqh[Mx*32], g_tql[Mx*32], g_tkh[Mx*32], g_tkl[Mx*32];
__device__ __align__(16) uint32_t g_qgh[Bx*HEADERx*Sx*32], g_qgl[Bx*HEADERx*Sx*32];
__device__ __align__(16) uint32_t g_kgh[Bx*HEADERx*Sx*32], g_kgl[Bx*HEADERx*Sx*32];
__device__ __align__(16) uint32_t g_qph[Bx*ESSx*Sx*32], g_qpl[Bx*ESSx*Sx*32];
__device__ __align__(16) uint32_t g_kph[Bx*ESSx*Sx*32], g_kpl[Bx*ESSx*Sx*32];
__device__ __align__(16) uint32_t g_adjh[(size_t)Bx*HEADERx*Sx*192], g_adjl[(size_t)Bx*HEADERx*Sx*192];
__device__ __align__(16) uint32_t g_hrh[(size_t)HEADERx*Hx*3072], g_hrl[(size_t)HEADERx*Hx*3072];
__device__ __align__(16) uint32_t g_feath[Mx*384], g_featl[Mx*384];
__device__ __align__(16) uint32_t g_inph[Mx*768], g_inpl[Mx*768];
__device__ __align__(16) uint32_t g_wAh[128*384],  g_wAl[128*384];
__device__ __align__(16) uint32_t g_wCh[1344*384], g_wCl[1344*384];
__device__ __align__(16) uint32_t g_wEh[2*576*336],g_wEl[2*576*336];
__device__ __align__(16) uint32_t g_wrh[2*9*768*384], g_wrl[2*9*768*384];
__device__ __align__(16) uint32_t g_wBh[128*768],  g_wBl[128*768];
__device__ __align__(16) uint32_t g_wDh[1920*768], g_wDl[1920*768];
__device__ __align__(16) uint32_t g_wFh[2*384*480],g_wFl[2*384*480];
__device__ float g_bA[128], g_bC[1344], g_bE[1152], g_bB[128], g_bD[1920], g_bF[768];

__device__ __forceinline__ void split2(float x0, float x1, uint32_t& h, uint32_t& l) {
    __half2 p = __floats2half2_rn(x0, x1);
    h = *reinterpret_cast<uint32_t*>(&p);
    float2 bk = __half22float2(p);
    __half2 q = __floats2half2_rn(x0 - bk.x, x1 - bk.y);
    l = *reinterpret_cast<uint32_t*>(&q);
}
__device__ __forceinline__ void mma_bf(float* d, const uint32_t* a, const uint32_t* b) {
    asm volatile(
        "mma.sync.aligned.m16n8k16.row.col.f32.f16.f16.f32 "
        "{%0,%1,%2,%3},{%4,%5,%6,%7},{%8,%9},{%0,%1,%2,%3};"
        : "+f"(d[0]), "+f"(d[1]), "+f"(d[2]), "+f"(d[3])
        : "r"(a[0]), "r"(a[1]), "r"(a[2]), "r"(a[3]), "r"(b[0]), "r"(b[1]));
}
__device__ __forceinline__ void ldsm4(uint32_t* r, uint32_t a) {
    asm volatile("ldmatrix.sync.aligned.m8n8.x4.shared.b16 {%0,%1,%2,%3},[%4];"
        : "=r"(r[0]), "=r"(r[1]), "=r"(r[2]), "=r"(r[3]) : "r"(a));
}
#define CPA(dst, src) asm volatile("cp.async.cg.shared.global [%0], [%1], 16;" :: "r"(dst), "l"(src))
#define CPAZ(dst, src, sz) asm volatile("cp.async.cg.shared.global [%0], [%1], 16, %2;" :: "r"(dst), "l"(src), "r"(sz))
#define CPC() asm volatile("cp.async.commit_group;" ::: "memory")
#define CPW(n) asm volatile("cp.async.wait_group %0;" :: "n"(n) : "memory")

__global__ void k_init_rope() {
    int idx = blockIdx.x * blockDim.x + threadIdx.x;
    if (idx >= Sx * 32) return;
    int p = idx / 32, i = idx & 31;
    double th = (double)p * pow(10000.0, -(double)i / 32.0);
    g_cos[idx] = (float)cos(th);
    g_sin[idx] = (float)sin(th);
}

__global__ void k_split(const float* __restrict__ in, uint32_t* __restrict__ h,
                        uint32_t* __restrict__ l, long np)
{
    long p = (long)blockIdx.x * blockDim.x + threadIdx.x;
    if (p >= np) return;
    float2 v = ((const float2*)in)[p];
    uint32_t hh, ll; split2(v.x, v.y, hh, ll);
    h[p] = hh; l[p] = ll;
}

// ---- split-fp16 GEMM: 128x128 CTA, 8 warps (2x4), 64x32 warp tiles,
//      2-term, K-step 32 (16 pairs, 2 halves), 2-stage, 2 CTAs/SM ----
// flags: 1=relu, 2=packed output, 4=skip lo store
__global__ void __launch_bounds__(256, 2) k_mma(
    const uint32_t* __restrict__ Ahg, const uint32_t* __restrict__ Alg, long az, int lda,
    const uint32_t* __restrict__ Whg, const uint32_t* __restrict__ Wlg, long wz, int ldw,
    const float* __restrict__ bias, int bz,
    float* __restrict__ C, uint32_t* __restrict__ Ch, uint32_t* __restrict__ Cl,
    long cz, int ldc, int N, int KP, int flags, float scale)
{
    __shared__ uint32_t SA[2][2][2][128][8];  // [buf][half][arr][row][pair] 32KB
    __shared__ uint32_t SB[2][2][128][8];     // [buf][half][row][pair] 16KB

    int tid = threadIdx.x, lane = tid & 31;
    int g = lane >> 2, tg = lane & 3;
    int wid = tid >> 5, wm = wid >> 2, wn = wid & 3;
    int row0 = blockIdx.y * 128, col0 = blockIdx.x * 128;
    long z = blockIdx.z;

    const uint32_t* A0 = Ahg + z * az;
    const uint32_t* A1 = Alg + z * az;
    const uint32_t* W0 = Whg + z * wz;

    uint32_t saB = (uint32_t)__cvta_generic_to_shared(SA);
    uint32_t sbB = (uint32_t)__cvta_generic_to_shared(SB);
    int lm = lane >> 3, ri = lane & 7;
    int stages = KP >> 4;

    float acc[4][4][4] = {};

#define FILL(s, buf) { \
    _Pragma("unroll") \
    for (int u = 0; u < 4; ++u) { \
        int i = tid + u * 256; \
        int arr = i >> 9, row = (i >> 2) & 127, q = i & 3; \
        int half = q >> 1, qq = q & 1; \
        uint32_t off = saB + (uint32_t)(buf) * 16384u + (uint32_t)half * 8192u \
                     + (uint32_t)arr * 4096u \
                     + ((uint32_t)row * 8u + ((4u * (uint32_t)qq) ^ (row & 4))) * 4u; \
        CPA(off, (arr ? A1 : A0) + (long)(row0 + row) * lda + (s) * 16 + 4 * q); \
    } \
    _Pragma("unroll") \
    for (int u = 0; u < 2; ++u) { \
        int i = tid + u * 256; \
        int row = (i >> 2) & 127, q = i & 3; \
        int half = q >> 1, qq = q & 1; \
        uint32_t off = sbB + (uint32_t)(buf) * 8192u + (uint32_t)half * 4096u \
                     + ((uint32_t)row * 8u + ((4u * (uint32_t)qq) ^ (row & 4))) * 4u; \
        int wr = col0 + row; \
        const uint32_t* src = W0 + (long)(wr < N ? wr : 0) * ldw + (s) * 16 + 4 * q; \
        CPAZ(off, src, (wr < N) ? 16 : 0); \
    } \
    CPC(); }

    FILL(0, 0);
    for (int t = 0; t < stages; ++t) {
        int cur = t & 1;
        if (t + 1 < stages) { FILL(t + 1, cur ^ 1); CPW(1); } else { CPW(0); }
        __syncthreads();

#pragma unroll
        for (int half = 0; half < 2; ++half) {
            uint32_t abase = saB + (uint32_t)cur * 16384u + (uint32_t)half * 8192u;
            uint32_t bbase = sbB + (uint32_t)cur * 8192u + (uint32_t)half * 4096u;
            uint32_t ah[4][4], al[4][4];
#pragma unroll
            for (int mt = 0; mt < 4; ++mt) {
                int arow = wm * 64 + mt * 16 + (lm & 1) * 8 + ri;
                uint32_t off = ((uint32_t)arow * 8u + ((4u * (uint32_t)(lm >> 1)) ^ (arow & 4))) * 4u;
                ldsm4(ah[mt], abase + off);
                ldsm4(al[mt], abase + 4096u + off);
            }
#pragma unroll
            for (int bq = 0; bq < 2; ++bq) {
                int brow = wn * 32 + bq * 16 + (lm >> 1) * 8 + ri;
                uint32_t boff = ((uint32_t)brow * 8u + ((4u * (uint32_t)(lm & 1)) ^ (brow & 4))) * 4u;
                uint32_t bh[4];
                ldsm4(bh, bbase + boff);
#pragma unroll
                for (int mt = 0; mt < 4; ++mt)
#pragma unroll
                    for (int hf = 0; hf < 2; ++hf) {
                        int nt = bq * 2 + hf;
                        mma_bf(acc[mt][nt], al[mt], bh + hf * 2);
                        mma_bf(acc[mt][nt], ah[mt], bh + hf * 2);
                    }
            }
        }
        __syncthreads();
    }
#undef FILL

    bool relu = flags & 1, packed = (flags & 2) != 0, wlo = !(flags & 4);
#pragma unroll
    for (int mt = 0; mt < 4; ++mt) {
        int r = row0 + wm * 64 + mt * 16 + g;
#pragma unroll
        for (int nt = 0; nt < 4; ++nt) {
            int c = col0 + wn * 32 + nt * 8 + 2 * tg;
            if (c < N) {
                float b0 = bias ? bias[z * bz + c] : 0.f;
                float b1 = bias ? bias[z * bz + c + 1] : 0.f;
                float v00 = acc[mt][nt][0] * scale + b0, v01 = acc[mt][nt][1] * scale + b1;
                float v10 = acc[mt][nt][2] * scale + b0, v11 = acc[mt][nt][3] * scale + b1;
                if (relu) {
                    v00 = fmaxf(v00, 0.f); v01 = fmaxf(v01, 0.f);
                    v10 = fmaxf(v10, 0.f); v11 = fmaxf(v11, 0.f);
                }
                if (packed) {
                    uint32_t hh, ll;
                    long o = z * cz + (long)r * ldc + (c >> 1);
                    split2(v00, v01, hh, ll); Ch[o] = hh; if (wlo) Cl[o] = ll;
                    o = z * cz + (long)(r + 8) * ldc + (c >> 1);
                    split2(v10, v11, hh, ll); Ch[o] = hh; if (wlo) Cl[o] = ll;
                } else {
                    *(float2*)&C[z * cz + (long)r * ldc + c] = make_float2(v00, v01);
                    *(float2*)&C[z * cz + (long)(r + 8) * ldc + c] = make_float2(v10, v11);
                }
            }
        }
    }
}

// ---- RGAT agg: CTA 128(s)x64(o), 8 warps (4x2), 2-term fp16, K-step 32,
//      register sum, 2 CTAs/SM ----
__global__ void __launch_bounds__(256, 2) k_agg(
    const uint32_t* __restrict__ adjh, const uint32_t* __restrict__ adjl,
    const uint32_t* __restrict__ hrh,
    float* __restrict__ out)
{
    __shared__ uint32_t SA[2][2][2][128][8];  // 32KB
    __shared__ uint32_t SB[2][2][64][8];      // 8KB (hi only)

    int b = blockIdx.z, row0 = blockIdx.y * 128, col0 = blockIdx.x * 64;
    int tid = threadIdx.x, lane = tid & 31;
    int g = lane >> 2, tg = lane & 3;
    int wid = tid >> 5, wm = wid >> 1, wn = wid & 1;
    int lm = lane >> 3, ri = lane & 7;

    uint32_t saB = (uint32_t)__cvta_generic_to_shared(SA);
    uint32_t sbB = (uint32_t)__cvta_generic_to_shared(SB);

    float sum[2][4][4] = {};

    for (int rel = 0; rel < HEADERx; ++rel) {
        const uint32_t* A0 = adjh + ((long)(b * HEADERx + rel) * Sx + row0) * 192;
        const uint32_t* A1 = adjl + ((long)(b * HEADERx + rel) * Sx + row0) * 192;
        const uint32_t* W0 = hrh + (long)(rel * Hx + col0) * 3072 + b * 192;
        float acc[2][4][4] = {};

#define FILLG(s, buf) { \
    _Pragma("unroll") \
    for (int u = 0; u < 4; ++u) { \
        int i = tid + u * 256; \
        int arr = i >> 9, row = (i >> 2) & 127, q = i & 3; \
        int half = q >> 1, qq = q & 1; \
        uint32_t off = saB + (uint32_t)(buf) * 16384u + (uint32_t)half * 8192u \
                     + (uint32_t)arr * 4096u \
                     + ((uint32_t)row * 8u + ((4u * (uint32_t)qq) ^ (row & 4))) * 4u; \
        CPA(off, (arr ? A1 : A0) + (long)row * 192 + (s) * 16 + 4 * q); \
    } \
    { \
        int i = tid; \
        int row = (i >> 2) & 63, q = i & 3; \
        int half = q >> 1, qq = q & 1; \
        uint32_t off = sbB + (uint32_t)(buf) * 4096u + (uint32_t)half * 2048u \
                     + ((uint32_t)row * 8u + ((4u * (uint32_t)qq) ^ (row & 4))) * 4u; \
        CPA(off, W0 + (long)row * 3072 + (s) * 16 + 4 * q); \
    } \
    CPC(); }

        FILLG(0, 0);
        for (int t = 0; t < 12; ++t) {      // 192 pairs / 16
            int cur = t & 1;
            if (t + 1 < 12) { FILLG(t + 1, cur ^ 1); CPW(1); } else { CPW(0); }
            __syncthreads();
#pragma unroll
            for (int half = 0; half < 2; ++half) {
                uint32_t abase = saB + (uint32_t)cur * 16384u + (uint32_t)half * 8192u;
                uint32_t bbase = sbB + (uint32_t)cur * 4096u + (uint32_t)half * 2048u;
                uint32_t ah[2][4], al[2][4];
#pragma unroll
                for (int mt = 0; mt < 2; ++mt) {
                    int arow = wm * 32 + mt * 16 + (lm & 1) * 8 + ri;
                    uint32_t off = ((uint32_t)arow * 8u + ((4u * (uint32_t)(lm >> 1)) ^ (arow & 4))) * 4u;
                    ldsm4(ah[mt], abase + off);
                    ldsm4(al[mt], abase + 4096u + off);
                }
#pragma unroll
                for (int bq = 0; bq < 2; ++bq) {
                    int brow = wn * 32 + bq * 16 + (lm >> 1) * 8 + ri;
                    uint32_t boff = ((uint32_t)brow * 8u + ((4u * (uint32_t)(lm & 1)) ^ (brow & 4))) * 4u;
                    uint32_t bh[4];
                    ldsm4(bh, bbase + boff);
#pragma unroll
                    for (int mt = 0; mt < 2; ++mt)
#pragma unroll
                        for (int hf = 0; hf < 2; ++hf) {
                            int nt = bq * 2 + hf;
                            mma_bf(acc[mt][nt], al[mt], bh + hf * 2);
                            mma_bf(acc[mt][nt], ah[mt], bh + hf * 2);
                        }
                }
            }
            __syncthreads();
        }
#undef FILLG
#pragma unroll
        for (int mt = 0; mt < 2; ++mt)
#pragma unroll
            for (int nt = 0; nt < 4; ++nt)
#pragma unroll
                for (int i = 0; i < 4; ++i)
                    sum[mt][nt][i] += fmaxf(acc[mt][nt][i], 0.f);
    }

#pragma unroll
    for (int mt = 0; mt < 2; ++mt) {
        int s = row0 + wm * 32 + mt * 16 + g;
#pragma unroll
        for (int nt = 0; nt < 4; ++nt) {
            int o = col0 + wn * 32 + nt * 8 + 2 * tg;
            *(float2*)&out[((long)b * Sx + s) * Hx + o] = make_float2(sum[mt][nt][0], sum[mt][nt][1]);
            *(float2*)&out[((long)b * Sx + s + 8) * Hx + o] = make_float2(sum[mt][nt][2], sum[mt][nt][3]);
        }
    }
}

__global__ void k_rope(const float* __restrict__ lin, const float* __restrict__ mask,
                       uint32_t* __restrict__ qh, uint32_t* __restrict__ ql,
                       int nH, int ld, int off)
{
    int bs = blockIdx.x, b = bs / Sx, s = bs % Sx;
    float m = mask[bs];
    int t = threadIdx.x, h = t >> 5, i = t & 31;
    float c = g_cos[s * 32 + i], sn = g_sin[s * 32 + i];
    const float* lp = lin + (long)bs * ld + off + h * 64 + 2 * i;
    float x0 = lp[0] * m, x1 = lp[1] * m;
    uint32_t hh, ll;
    split2(x0 * c - x1 * sn, x1 * c + x0 * sn, hh, ll);
    long o = ((long)(b * nH + h) * Sx + s) * 32 + i;
    qh[o] = hh; ql[o] = ll;
}

__global__ void k_sym(float* __restrict__ scg)
{
    int tj = blockIdx.x, ti = blockIdx.y, z = blockIdx.z;
    if (ti < tj) return;
    __shared__ float s[32][33];
    float* m = scg + (long)z * SSx;
    int tx = threadIdx.x;
    for (int a = threadIdx.y; a < 32; a += 8)
        s[a][tx] = m[(long)(tj * 32 + a) * Sx + ti * 32 + tx];
    __syncthreads();
    for (int a = threadIdx.y; a < 32; a += 8) {
        int i = ti * 32 + a, j = tj * 32 + tx;
        if (ti > tj || tx < a) m[(long)i * Sx + j] = s[tx][a];
    }
}

__global__ void k_adj(const float* __restrict__ scg,
                      uint32_t* __restrict__ adjh, uint32_t* __restrict__ adjl)
{
    int i = blockIdx.x % Sx;
    long bh = blockIdx.x / Sx;
    const float* row = scg + bh * SSx + (long)i * Sx;
    int t = threadIdx.x, lane = t & 31, w = t >> 5;
    float2 v = *(const float2*)&row[2 * t];
    __shared__ float red[6], red2[6];
    float m = fmaxf(v.x, v.y);
#pragma unroll
    for (int o = 16; o > 0; o >>= 1) m = fmaxf(m, __shfl_xor_sync(~0u, m, o));
    if (lane == 0) red[w] = m;
    __syncthreads();
    m = fmaxf(fmaxf(fmaxf(red[0], red[1]), fmaxf(red[2], red[3])), fmaxf(red[4], red[5]));
    float e0 = expf(v.x - m), e1 = expf(v.y - m), s = e0 + e1;
#pragma unroll
    for (int o = 16; o > 0; o >>= 1) s += __shfl_xor_sync(~0u, s, o);
    if (lane == 0) red2[w] = s;
    __syncthreads();
    s = red2[0] + red2[1] + red2[2] + red2[3] + red2[4] + red2[5];
    float is = 1.f / s;
    uint32_t hh, ll;
    split2((v.x != 0.f) ? e0 * is : 0.f, (v.y != 0.f) ? e1 * is : 0.f, hh, ll);
    long o = (bh * Sx + i) * 192 + t;
    adjh[o] = hh; adjl[o] = ll;
}

__global__ void k_ln(const float* __restrict__ agg, uint32_t* __restrict__ fh,
                     uint32_t* __restrict__ fl)
{
    long row = blockIdx.x;
    int t = threadIdx.x, lane = t & 31, w = t >> 5;
    float2 xv = *(const float2*)&agg[row * Hx + 2 * t];
    float v0 = fmaxf(xv.x, 0.f) * (1.f / 9.f);
    float v1 = fmaxf(xv.y, 0.f) * (1.f / 9.f);
    __shared__ float red[12], red2[12];
    float s = v0 + v1;
#pragma unroll
    for (int o = 16; o > 0; o >>= 1) s += __shfl_xor_sync(~0u, s, o);
    if (lane == 0) red[w] = s;
    __syncthreads();
    float tot = 0.f;
#pragma unroll
    for (int u = 0; u < 12; ++u) tot += red[u];
    float mean = tot * (1.f / 768.f);
    float d0 = v0 - mean, d1 = v1 - mean, s2 = d0 * d0 + d1 * d1;
#pragma unroll
    for (int o = 16; o > 0; o >>= 1) s2 += __shfl_xor_sync(~0u, s2, o);
    if (lane == 0) red2[w] = s2;
    __syncthreads();
    float tv = 0.f;
#pragma unroll
    for (int u = 0; u < 12; ++u) tv += red2[u];
    float rr = rsqrtf(tv * (1.f / 768.f) + 1e-5f);
    uint32_t hh, ll;
    split2(d0 * rr, d1 * rr, hh, ll);
    fh[row * 384 + t] = hh; fl[row * 384 + t] = ll;
}

__global__ void k_concat(const uint32_t* __restrict__ xh, const uint32_t* __restrict__ xl,
                         const uint32_t* __restrict__ fh, const uint32_t* __restrict__ fl,
                         uint32_t* __restrict__ ih, uint32_t* __restrict__ il)
{
    long idx = (long)blockIdx.x * blockDim.x + threadIdx.x;
    if (idx >= (long)Mx * 768) return;
    long row = idx / 768;
    int c = (int)(idx % 768);
    long src = row * 384 + (c < 384 ? c : c - 384);
    ih[idx] = (c < 384) ? xh[src] : fh[src];
    il[idx] = (c < 384) ? xl[src] : fl[src];
}

__global__ void k_pairs(const float* __restrict__ sp, const float* __restrict__ stp,
                        const float* __restrict__ sg, const float* __restrict__ stg,
                        float* __restrict__ out)
{
    int i = blockIdx.x, b = blockIdx.y, j = threadIdx.x;
    if (j < i) return;
    long p = (long)i * (2 * Sx - i + 1) / 2 + (j - i);
    long ss = SSx, ij = (long)i * Sx + j;
    const float* spb = sp + (long)b * ESSx * ss + ij;
    const float* sgb = sg + (long)b * HEADERx * ss + ij;
    float4 o0, o1, o2, o3;
    o0.x = spb[0];    o0.y = spb[ss];   o0.z = spb[2*ss]; o0.w = spb[3*ss];
    o1.x = spb[4*ss]; o1.y = spb[5*ss];
    o1.z = fmaxf(stp[(long)b*ss + ij], 0.f);
    o1.w = sgb[0];
    o2.x = sgb[ss];   o2.y = sgb[2*ss]; o2.z = sgb[3*ss]; o2.w = sgb[4*ss];
    o3.x = sgb[5*ss]; o3.y = sgb[6*ss]; o3.z = sgb[7*ss];
    o3.w = fmaxf(stg[(long)b*ss + ij], 0.f);
    float4* op = (float4*)(out + ((long)b * Px + p) * 16);
    op[0] = o0; op[1] = o1; op[2] = o2; op[3] = o3;
}

#define SYM(p, s) cudaGetSymbolAddress((void**)&p, s)

static void gsplit(const float* src, uint32_t* h, uint32_t* l, long elems) {
    long np = elems / 2;
    k_split<<<(int)((np + 255) / 256), 256>>>(src, h, l, np);
}
static void gemm(const uint32_t* Ah, const uint32_t* Al, long az, int lda,
                 const uint32_t* Wh, const uint32_t* Wl, long wz, int ldw,
                 const float* bias, int bz,
                 float* C, uint32_t* Ch, uint32_t* Cl, long cz, int ldc,
                 int M, int N, int KP, int flags, float scale, int Z)
{
    dim3 grid((N + 127) / 128, M / 128, Z);
    k_mma<<<grid, 256>>>(Ah, Al, az, lda, Wh, Wl, wz, ldw, bias, bz,
                         C, Ch, Cl, cz, ldc, N, KP, flags, scale);
}

extern "C" void kernel_launch(void* const* d_in, const int* in_sizes, int n_in,
                              void* d_out, int out_size)
{
    const float* x      = (const float*)d_in[0];
    const float* amask  = (const float*)d_in[1];
    const float* w1 = (const float*)d_in[2];   const float* b1 = (const float*)d_in[3];
    const float* w2 = (const float*)d_in[4];   const float* b2 = (const float*)d_in[5];
    const float* w3 = (const float*)d_in[6];   const float* b3 = (const float*)d_in[7];
    const float* w5 = (const float*)d_in[8];   const float* b5 = (const float*)d_in[9];
    const float* w4 = (const float*)d_in[10];  const float* b4 = (const float*)d_in[11];
    const float* w6 = (const float*)d_in[12];  const float* b6 = (const float*)d_in[13];
    const float* rgat_w = (const float*)d_in[14];
    const float* w7 = (const float*)d_in[15];  const float* b7 = (const float*)d_in[16];
    const float* w8 = (const float*)d_in[17];  const float* b8 = (const float*)d_in[18];
    const float* w9 = (const float*)d_in[19];  const float* b9 = (const float*)d_in[20];
    const float* w11 = (const float*)d_in[21]; const float* b11 = (const float*)d_in[22];
    const float* w10 = (const float*)d_in[23]; const float* b10 = (const float*)d_in[24];
    const float* w12 = (const float*)d_in[25]; const float* b12 = (const float*)d_in[26];
    float* out = (float*)d_out;

    float *lin, *lin2, *scg, *stg, *stp, *sp, *agg;
    SYM(lin, g_lin); SYM(lin2, g_lin2); SYM(scg, g_scg); SYM(stg, g_stg);
    SYM(stp, g_stp); SYM(sp, g_sp); SYM(agg, g_agg);
    uint32_t *xh,*xl,*hidh,*hidl,*tsqh,*tsql,*tskh,*tskl,*tqh,*tql,*tkh,*tkl;
    uint32_t *qgh,*qgl,*kgh,*kgl,*qph,*qpl,*kph,*kpl,*adjh,*adjl,*hrh,*hrl;
    uint32_t *feath,*featl,*inph,*inpl;
    uint32_t *wAh,*wAl,*wCh,*wCl,*wEh,*wEl,*wrh,*wrl,*wBh,*wBl,*wDh,*wDl,*wFh,*wFl;
    float *bA,*bC,*bE,*bB,*bD,*bF;
    SYM(xh,g_xh); SYM(xl,g_xl); SYM(hidh,g_hidh); SYM(hidl,g_hidl);
    SYM(tsqh,g_tsqh); SYM(tsql,g_tsql); SYM(tskh,g_tskh); SYM(tskl,g_tskl);
    SYM(tqh,g_tqh); SYM(tql,g_tql); SYM(tkh,g_tkh); SYM(tkl,g_tkl);
    SYM(qgh,g_qgh); SYM(qgl,g_qgl); SYM(kgh,g_kgh); SYM(kgl,g_kgl);
    SYM(qph,g_qph); SYM(qpl,g_qpl); SYM(kph,g_kph); SYM(kpl,g_kpl);
    SYM(adjh,g_adjh); SYM(adjl,g_adjl); SYM(hrh,g_hrh); SYM(hrl,g_hrl);
    SYM(feath,g_feath); SYM(featl,g_featl); SYM(inph,g_inph); SYM(inpl,g_inpl);
    SYM(wAh,g_wAh); SYM(wAl,g_wAl); SYM(wCh,g_wCh); SYM(wCl,g_wCl);
    SYM(wEh,g_wEh); SYM(wEl,g_wEl); SYM(wrh,g_wrh); SYM(wrl,g_wrl);
    SYM(wBh,g_wBh); SYM(wBl,g_wBl); SYM(wDh,g_wDh); SYM(wDl,g_wDl);
    SYM(wFh,g_wFh); SYM(wFl,g_wFl);
    SYM(bA,g_bA); SYM(bC,g_bC); SYM(bE,g_bE); SYM(bB,g_bB); SYM(bD,g_bD); SYM(bF,g_bF);

    const float inv = 0.125f;
    const long qs = (long)Sx * 32;

    k_init_rope<<<48, 256>>>();
    gsplit(x, xh, xl, (long)Mx * 768);
    gsplit(rgat_w, wrh, wrl, (long)2 * 9 * 768 * 768);
    gemm(wrh, wrl, (long)768 * 384, 384, xh, xl, 0, 384, 0, 0,
         0, hrh, hrl, (long)768 * 3072, 3072, Hx, Mx, 384, 6, 1.f, 5);
    gemm(wrh + (long)5 * 768 * 384, wrl + (long)5 * 768 * 384, (long)768 * 384, 384,
         xh, xl, 0, 384, 0, 0,
         0, hrh + (long)5 * 768 * 3072, hrl + (long)5 * 768 * 3072,
         (long)768 * 3072, 3072, Hx, Mx, 384, 6, 1.f, 4);

    gsplit(w1, wAh, wAl, 64 * 768);
    gsplit(w2, wAh + 64 * 384, wAl + 64 * 384, 64 * 768);
    gsplit(w3, wCh, wCl, 672 * 768);
    gsplit(w4, wCh + 672 * 384, wCl + 672 * 384, 672 * 768);
    gsplit(w5, wEh, wEl, 576 * 672);
    gsplit(w6, wEh + 576 * 336, wEl + 576 * 336, 576 * 672);
    gsplit(w7, wBh, wBl, 64 * 1536);
    gsplit(w8, wBh + 64 * 768, wBl + 64 * 768, 64 * 1536);
    gsplit(w9, wDh, wDl, 960 * 1536);
    gsplit(w10, wDh + 960 * 768, wDl + 960 * 768, 960 * 1536);
    gsplit(w11, wFh, wFl, 384 * 960);
    gsplit(w12, wFh + 384 * 480, wFl + 384 * 480, 384 * 960);
    cudaMemcpyAsync(bA, b1, 64*4, cudaMemcpyDeviceToDevice);
    cudaMemcpyAsync(bA+64, b2, 64*4, cudaMemcpyDeviceToDevice);
    cudaMemcpyAsync(bC, b3, 672*4, cudaMemcpyDeviceToDevice);
    cudaMemcpyAsync(bC+672, b4, 672*4, cudaMemcpyDeviceToDevice);
    cudaMemcpyAsync(bE, b5, 576*4, cudaMemcpyDeviceToDevice);
    cudaMemcpyAsync(bE+576, b6, 576*4, cudaMemcpyDeviceToDevice);
    cudaMemcpyAsync(bB, b7, 64*4, cudaMemcpyDeviceToDevice);
    cudaMemcpyAsync(bB+64, b8, 64*4, cudaMemcpyDeviceToDevice);
    cudaMemcpyAsync(bD, b9, 960*4, cudaMemcpyDeviceToDevice);
    cudaMemcpyAsync(bD+960, b10, 960*4, cudaMemcpyDeviceToDevice);
    cudaMemcpyAsync(bF, b11, 384*4, cudaMemcpyDeviceToDevice);
    cudaMemcpyAsync(bF+384, b12, 384*4, cudaMemcpyDeviceToDevice);

    gemm(xh, xl, 0, 384, wAh, wAl, 0, 384, bA, 0, lin, 0, 0, 0, 128,
         Mx, 128, 384, 0, 1.f, 1);
    k_rope<<<Mx, 32>>>(lin, amask, tsqh, tsql, 1, 128, 0);
    k_rope<<<Mx, 32>>>(lin, amask, tskh, tskl, 1, 128, 64);
    gemm(tsqh, tsql, qs, 32, tskh, tskl, qs, 32, 0, 0, stg, 0, 0, SSx, Sx,
         Sx, Sx, 32, 0, inv, Bx);

    gemm(xh, xl, 0, 384, wCh, wCl, 0, 384, bC, 0, 0, hidh, hidl, 0, 672,
         Mx, 1344, 384, 3, 1.f, 1);
    gemm(hidh, hidl, 336, 672, wEh, wEl, (long)576 * 336, 336, bE, 576,
         lin2, 0, 0, (long)Mx * 576, 576, Mx, 576, 336, 0, 1.f, 2);
    k_rope<<<Mx, 288>>>(lin2, amask, qgh, qgl, 9, 576, 0);
    k_rope<<<Mx, 288>>>(lin2 + (long)Mx * 576, amask, kgh, kgl, 9, 576, 0);
    gemm(qgh, qgl, qs, 32, kgh, kgl, qs, 32, 0, 0, scg, 0, 0, SSx, Sx,
         Sx, Sx, 32, 0, inv, Bx * HEADERx);
    k_sym<<<dim3(12, 12, Bx * HEADERx), dim3(32, 8)>>>(scg);
    k_adj<<<Bx * HEADERx * Sx, 192>>>(scg, adjh, adjl);

    k_agg<<<dim3(12, 3, Bx), 256>>>(adjh, adjl, hrh, agg);
    k_ln<<<Mx, 384>>>(agg, feath, featl);
    gemm(wrh + (long)9 * 768 * 384, wrl + (long)9 * 768 * 384, (long)768 * 384, 384,
         feath, featl, 0, 384, 0, 0, 0, hrh, hrl, (long)768 * 3072, 3072,
         Hx, Mx, 384, 6, 1.f, HEADERx);
    k_agg<<<dim3(12, 3, Bx), 256>>>(adjh, adjl, hrh, agg);
    k_ln<<<Mx, 384>>>(agg, feath, featl);

    k_concat<<<(int)(((long)Mx * 768 + 255) / 256), 256>>>(xh, xl, feath, featl, inph, inpl);

    gemm(inph, inpl, 0, 768, wBh, wBl, 0, 768, bB, 0, lin, 0, 0, 0, 128,
         Mx, 128, 768, 0, 1.f, 1);
    k_rope<<<Mx, 32>>>(lin, amask, tqh, tql, 1, 128, 0);
    k_rope<<<Mx, 32>>>(lin, amask, tkh, tkl, 1, 128, 64);
    gemm(tqh, tql, qs, 32, tkh, tkl, qs, 32, 0, 0, stp, 0, 0, SSx, Sx,
         Sx, Sx, 32, 0, inv, Bx);

    gemm(inph, inpl, 0, 768, wDh, wDl, 0, 768, bD, 0, 0, hidh, hidl, 0, 960,
         Mx, 1920, 768, 3, 1.f, 1);
    gemm(hidh, hidl, 480, 960, wFh, wFl, (long)384 * 480, 480, bF, 384,
         lin2, 0, 0, (long)Mx * 384, 384, Mx, 384, 480, 0, 1.f, 2);
    k_rope<<<Mx, 192>>>(lin2, amask, qph, qpl, 6, 384, 0);
    k_rope<<<Mx, 192>>>(lin2 + (long)Mx * 384, amask, kph, kpl, 6, 384, 0);
    gemm(qph, qpl, qs, 32, kph, kpl, qs, 32, 0, 0, sp, 0, 0, SSx, Sx,
         Sx, Sx, 32, 0, inv, Bx * ESSx);

    k_pairs<<<dim3(Sx, Bx), Sx>>>(sp, stp, scg, stg, out);
}

// round 17
// speedup vs baseline: 1.1483x; 1.1483x over previous
#include <cuda_runtime.h>
#include <cuda_fp16.h>
#include <math.h>
#include <stdint.h>

#define Bx 16
#define Sx 384
#define Hx 768
#define ESSx 6
#define HEADERx 9
#define Px 73920
#define Mx (Bx*Sx)
#define SSx ((long)Sx*Sx)

__device__ float g_cos[Sx*32];
__device__ float g_sin[Sx*32];
__device__ __align__(16) float g_lin[Mx*128];
__device__ __align__(16) float g_lin2[2*Mx*576];
__device__ __align__(16) float g_scg[(size_t)Bx*HEADERx*Sx*Sx];
__device__ __align__(16) float g_stg[(size_t)Bx*Sx*Sx];
__device__ __align__(16) float g_stp[(size_t)Bx*Sx*Sx];
__device__ __align__(16) float g_sp [(size_t)Bx*ESSx*Sx*Sx];
__device__ __align__(16) float g_agg[Mx*Hx];

__device__ __align__(16) uint32_t g_xh[Mx*384], g_xl[Mx*384];
__device__ __align__(16) uint32_t g_hidh[Mx*960], g_hidl[Mx*960];
__device__ __align__(16) uint32_t g_tsqh[Mx*32], g_tsql[Mx*32], g_tskh[Mx*32], g_tskl[Mx*32];
__device__ __align__(16) uint32_t g_tqh[Mx*32], g_tql[Mx*32], g_tkh[Mx*32], g_tkl[Mx*32];
__device__ __align__(16) uint32_t g_qgh[Bx*HEADERx*Sx*32], g_qgl[Bx*HEADERx*Sx*32];
__device__ __align__(16) uint32_t g_kgh[Bx*HEADERx*Sx*32], g_kgl[Bx*HEADERx*Sx*32];
__device__ __align__(16) uint32_t g_qph[Bx*ESSx*Sx*32], g_qpl[Bx*ESSx*Sx*32];
__device__ __align__(16) uint32_t g_kph[Bx*ESSx*Sx*32], g_kpl[Bx*ESSx*Sx*32];
__device__ __align__(16) uint32_t g_adjh[(size_t)Bx*HEADERx*Sx*192], g_adjl[(size_t)Bx*HEADERx*Sx*192];
__device__ __align__(16) uint32_t g_hrh[(size_t)HEADERx*Hx*3072], g_hrl[(size_t)HEADERx*Hx*3072];
__device__ __align__(16) uint32_t g_feath[Mx*384], g_featl[Mx*384];
__device__ __align__(16) uint32_t g_inph[Mx*768], g_inpl[Mx*768];
__device__ __align__(16) uint32_t g_wAh[128*384],  g_wAl[128*384];
__device__ __align__(16) uint32_t g_wCh[1344*384], g_wCl[1344*384];
__device__ __align__(16) uint32_t g_wEh[2*576*336],g_wEl[2*576*336];
__device__ __align__(16) uint32_t g_wrh[2*9*768*384], g_wrl[2*9*768*384];
__device__ __align__(16) uint32_t g_wBh[128*768],  g_wBl[128*768];
__device__ __align__(16) uint32_t g_wDh[1920*768], g_wDl[1920*768];
__device__ __align__(16) uint32_t g_wFh[2*384*480],g_wFl[2*384*480];
__device__ float g_bA[128], g_bC[1344], g_bE[1152], g_bB[128], g_bD[1920], g_bF[768];

__device__ __forceinline__ void split2(float x0, float x1, uint32_t& h, uint32_t& l) {
    __half2 p = __floats2half2_rn(x0, x1);
    h = *reinterpret_cast<uint32_t*>(&p);
    float2 bk = __half22float2(p);
    __half2 q = __floats2half2_rn(x0 - bk.x, x1 - bk.y);
    l = *reinterpret_cast<uint32_t*>(&q);
}
__device__ __forceinline__ void mma_bf(float* d, const uint32_t* a, const uint32_t* b) {
    asm volatile(
        "mma.sync.aligned.m16n8k16.row.col.f32.f16.f16.f32 "
        "{%0,%1,%2,%3},{%4,%5,%6,%7},{%8,%9},{%0,%1,%2,%3};"
        : "+f"(d[0]), "+f"(d[1]), "+f"(d[2]), "+f"(d[3])
        : "r"(a[0]), "r"(a[1]), "r"(a[2]), "r"(a[3]), "r"(b[0]), "r"(b[1]));
}
__device__ __forceinline__ void ldsm4(uint32_t* r, uint32_t a) {
    asm volatile("ldmatrix.sync.aligned.m8n8.x4.shared.b16 {%0,%1,%2,%3},[%4];"
        : "=r"(r[0]), "=r"(r[1]), "=r"(r[2]), "=r"(r[3]) : "r"(a));
}
#define CPA(dst, src) asm volatile("cp.async.cg.shared.global [%0], [%1], 16;" :: "r"(dst), "l"(src))
#define CPAZ(dst, src, sz) asm volatile("cp.async.cg.shared.global [%0], [%1], 16, %2;" :: "r"(dst), "l"(src), "r"(sz))
#define CPC() asm volatile("cp.async.commit_group;" ::: "memory")
#define CPW(n) asm volatile("cp.async.wait_group %0;" :: "n"(n) : "memory")

__global__ void k_init_rope() {
    int idx = blockIdx.x * blockDim.x + threadIdx.x;
    if (idx >= Sx * 32) return;
    int p = idx / 32, i = idx & 31;
    double th = (double)p * pow(10000.0, -(double)i / 32.0);
    g_cos[idx] = (float)cos(th);
    g_sin[idx] = (float)sin(th);
}

__global__ void k_split(const float* __restrict__ in, uint32_t* __restrict__ h,
                        uint32_t* __restrict__ l, long np)
{
    long p = (long)blockIdx.x * blockDim.x + threadIdx.x;
    if (p >= np) return;
    float2 v = ((const float2*)in)[p];
    uint32_t hh, ll; split2(v.x, v.y, hh, ll);
    h[p] = hh; l[p] = ll;
}

// ---- split-fp16 GEMM: 128x128 CTA, 8 warps (4x2), 32x64 warp tiles,
//      2-term, K-step 16, 2-stage, 2 CTAs/SM ----
// flags: 1=relu, 2=packed output, 4=skip lo store
__global__ void __launch_bounds__(256, 2) k_mma(
    const uint32_t* __restrict__ Ahg, const uint32_t* __restrict__ Alg, long az, int lda,
    const uint32_t* __restrict__ Whg, const uint32_t* __restrict__ Wlg, long wz, int ldw,
    const float* __restrict__ bias, int bz,
    float* __restrict__ C, uint32_t* __restrict__ Ch, uint32_t* __restrict__ Cl,
    long cz, int ldc, int N, int KP, int flags, float scale)
{
    __shared__ uint32_t SA[2][2][128][8];   // 16KB
    __shared__ uint32_t SB[2][128][8];      // 8KB (hi only)

    int tid = threadIdx.x, lane = tid & 31;
    int g = lane >> 2, tg = lane & 3;
    int wid = tid >> 5, wm = wid >> 1, wn = wid & 1;
    int row0 = blockIdx.y * 128, col0 = blockIdx.x * 128;
    long z = blockIdx.z;

    const uint32_t* A0 = Ahg + z * az;
    const uint32_t* A1 = Alg + z * az;
    const uint32_t* W0 = Whg + z * wz;

    uint32_t saB = (uint32_t)__cvta_generic_to_shared(SA);
    uint32_t sbB = (uint32_t)__cvta_generic_to_shared(SB);
    int lm = lane >> 3, ri = lane & 7;
    int stages = KP >> 3;

    float acc[2][8][4] = {};

#define FILL(s, buf) { \
    _Pragma("unroll") \
    for (int u = 0; u < 2; ++u) { \
        int i = tid + u * 256; int arr = i >> 8, row = (i >> 1) & 127, q = i & 1; \
        uint32_t off = saB + (uint32_t)(buf) * 8192u + (uint32_t)arr * 4096u \
                     + ((uint32_t)row * 8u + ((4u * (uint32_t)q) ^ (row & 4))) * 4u; \
        CPA(off, (arr ? A1 : A0) + (long)(row0 + row) * lda + (s) * 8 + 4 * q); \
    } \
    { \
        int i = tid; int row = (i >> 1) & 127, q = i & 1; \
        uint32_t off = sbB + (uint32_t)(buf) * 4096u \
                     + ((uint32_t)row * 8u + ((4u * (uint32_t)q) ^ (row & 4))) * 4u; \
        int wr = col0 + row; \
        const uint32_t* src = W0 + (long)(wr < N ? wr : 0) * ldw + (s) * 8 + 4 * q; \
        CPAZ(off, src, (wr < N) ? 16 : 0); \
    } \
    CPC(); }

    FILL(0, 0);
    for (int t = 0; t < stages; ++t) {
        int cur = t & 1;
        if (t + 1 < stages) { FILL(t + 1, cur ^ 1); CPW(1); } else { CPW(0); }
        __syncthreads();

        uint32_t ah[2][4], al[2][4];
#pragma unroll
        for (int mt = 0; mt < 2; ++mt) {
            int arow = wm * 32 + mt * 16 + (lm & 1) * 8 + ri;
            uint32_t off = ((uint32_t)arow * 8u + ((4u * (uint32_t)(lm >> 1)) ^ (arow & 4))) * 4u;
            ldsm4(ah[mt], saB + (uint32_t)cur * 8192u + off);
            ldsm4(al[mt], saB + (uint32_t)cur * 8192u + 4096u + off);
        }
#pragma unroll
        for (int bq = 0; bq < 4; ++bq) {
            int brow = wn * 64 + bq * 16 + (lm >> 1) * 8 + ri;
            uint32_t boff = ((uint32_t)brow * 8u + ((4u * (uint32_t)(lm & 1)) ^ (brow & 4))) * 4u;
            uint32_t bh[4];
            ldsm4(bh, sbB + (uint32_t)cur * 4096u + boff);
#pragma unroll
            for (int mt = 0; mt < 2; ++mt)
#pragma unroll
                for (int hf = 0; hf < 2; ++hf) {
                    int nt = bq * 2 + hf;
                    mma_bf(acc[mt][nt], al[mt], bh + hf * 2);
                    mma_bf(acc[mt][nt], ah[mt], bh + hf * 2);
                }
        }
        __syncthreads();
    }
#undef FILL

    bool relu = flags & 1, packed = (flags & 2) != 0, wlo = !(flags & 4);
#pragma unroll
    for (int mt = 0; mt < 2; ++mt) {
        int r = row0 + wm * 32 + mt * 16 + g;
#pragma unroll
        for (int nt = 0; nt < 8; ++nt) {
            int c = col0 + wn * 64 + nt * 8 + 2 * tg;
            if (c < N) {
                float b0 = bias ? bias[z * bz + c] : 0.f;
                float b1 = bias ? bias[z * bz + c + 1] : 0.f;
                float v00 = acc[mt][nt][0] * scale + b0, v01 = acc[mt][nt][1] * scale + b1;
                float v10 = acc[mt][nt][2] * scale + b0, v11 = acc[mt][nt][3] * scale + b1;
                if (relu) {
                    v00 = fmaxf(v00, 0.f); v01 = fmaxf(v01, 0.f);
                    v10 = fmaxf(v10, 0.f); v11 = fmaxf(v11, 0.f);
                }
                if (packed) {
                    uint32_t hh, ll;
                    long o = z * cz + (long)r * ldc + (c >> 1);
                    split2(v00, v01, hh, ll); Ch[o] = hh; if (wlo) Cl[o] = ll;
                    o = z * cz + (long)(r + 8) * ldc + (c >> 1);
                    split2(v10, v11, hh, ll); Ch[o] = hh; if (wlo) Cl[o] = ll;
                } else {
                    *(float2*)&C[z * cz + (long)r * ldc + c] = make_float2(v00, v01);
                    *(float2*)&C[z * cz + (long)(r + 8) * ldc + c] = make_float2(v10, v11);
                }
            }
        }
    }
}

// ---- RGAT agg: CTA 128(s)x64(o), 8 warps (4x2), 2-term fp16, K16, register sum ----
__global__ void __launch_bounds__(256, 2) k_agg(
    const uint32_t* __restrict__ adjh, const uint32_t* __restrict__ adjl,
    const uint32_t* __restrict__ hrh,
    float* __restrict__ out)
{
    __shared__ uint32_t SA[2][2][128][8];   // 16KB
    __shared__ uint32_t SB[2][64][8];       // 4KB (hi only)

    int b = blockIdx.z, row0 = blockIdx.y * 128, col0 = blockIdx.x * 64;
    int tid = threadIdx.x, lane = tid & 31;
    int g = lane >> 2, tg = lane & 3;
    int wid = tid >> 5, wm = wid >> 1, wn = wid & 1;
    int lm = lane >> 3, ri = lane & 7;

    uint32_t saB = (uint32_t)__cvta_generic_to_shared(SA);
    uint32_t sbB = (uint32_t)__cvta_generic_to_shared(SB);

    float sum[2][4][4] = {};

    for (int rel = 0; rel < HEADERx; ++rel) {
        const uint32_t* A0 = adjh + ((long)(b * HEADERx + rel) * Sx + row0) * 192;
        const uint32_t* A1 = adjl + ((long)(b * HEADERx + rel) * Sx + row0) * 192;
        const uint32_t* W0 = hrh + (long)(rel * Hx + col0) * 3072 + b * 192;
        float acc[2][4][4] = {};

#define FILLG(s, buf) { \
    _Pragma("unroll") \
    for (int u = 0; u < 2; ++u) { \
        int i = tid + u * 256; int arr = i >> 8, row = (i >> 1) & 127, q = i & 1; \
        uint32_t off = saB + (uint32_t)(buf) * 8192u + (uint32_t)arr * 4096u \
                     + ((uint32_t)row * 8u + ((4u * (uint32_t)q) ^ (row & 4))) * 4u; \
        CPA(off, (arr ? A1 : A0) + (long)row * 192 + (s) * 8 + 4 * q); \
    } \
    if (tid < 128) { \
        int row = (tid >> 1) & 63, q = tid & 1; \
        uint32_t off = sbB + (uint32_t)(buf) * 2048u \
                     + ((uint32_t)row * 8u + ((4u * (uint32_t)q) ^ (row & 4))) * 4u; \
        CPA(off, W0 + (long)row * 3072 + (s) * 8 + 4 * q); \
    } \
    CPC(); }

        FILLG(0, 0);
        for (int t = 0; t < 24; ++t) {
            int cur = t & 1;
            if (t + 1 < 24) { FILLG(t + 1, cur ^ 1); CPW(1); } else { CPW(0); }
            __syncthreads();
            uint32_t ah[2][4], al[2][4];
#pragma unroll
            for (int mt = 0; mt < 2; ++mt) {
                int arow = wm * 32 + mt * 16 + (lm & 1) * 8 + ri;
                uint32_t off = ((uint32_t)arow * 8u + ((4u * (uint32_t)(lm >> 1)) ^ (arow & 4))) * 4u;
                ldsm4(ah[mt], saB + (uint32_t)cur * 8192u + off);
                ldsm4(al[mt], saB + (uint32_t)cur * 8192u + 4096u + off);
            }
#pragma unroll
            for (int bq = 0; bq < 2; ++bq) {
                int brow = wn * 32 + bq * 16 + (lm >> 1) * 8 + ri;
                uint32_t boff = ((uint32_t)brow * 8u + ((4u * (uint32_t)(lm & 1)) ^ (brow & 4))) * 4u;
                uint32_t bh[4];
                ldsm4(bh, sbB + (uint32_t)cur * 2048u + boff);
#pragma unroll
                for (int mt = 0; mt < 2; ++mt)
#pragma unroll
                    for (int hf = 0; hf < 2; ++hf) {
                        int nt = bq * 2 + hf;
                        mma_bf(acc[mt][nt], al[mt], bh + hf * 2);
                        mma_bf(acc[mt][nt], ah[mt], bh + hf * 2);
                    }
            }
            __syncthreads();
        }
#undef FILLG
#pragma unroll
        for (int mt = 0; mt < 2; ++mt)
#pragma unroll
            for (int nt = 0; nt < 4; ++nt)
#pragma unroll
                for (int i = 0; i < 4; ++i)
                    sum[mt][nt][i] += fmaxf(acc[mt][nt][i], 0.f);
    }

#pragma unroll
    for (int mt = 0; mt < 2; ++mt) {
        int s = row0 + wm * 32 + mt * 16 + g;
#pragma unroll
        for (int nt = 0; nt < 4; ++nt) {
            int o = col0 + wn * 32 + nt * 8 + 2 * tg;
            *(float2*)&out[((long)b * Sx + s) * Hx + o] = make_float2(sum[mt][nt][0], sum[mt][nt][1]);
            *(float2*)&out[((long)b * Sx + s + 8) * Hx + o] = make_float2(sum[mt][nt][2], sum[mt][nt][3]);
        }
    }
}

__global__ void k_rope(const float* __restrict__ lin, const float* __restrict__ mask,
                       uint32_t* __restrict__ qh, uint32_t* __restrict__ ql,
                       int nH, int ld, int off)
{
    int bs = blockIdx.x, b = bs / Sx, s = bs % Sx;
    float m = mask[bs];
    int t = threadIdx.x, h = t >> 5, i = t & 31;
    float c = g_cos[s * 32 + i], sn = g_sin[s * 32 + i];
    const float* lp = lin + (long)bs * ld + off + h * 64 + 2 * i;
    float x0 = lp[0] * m, x1 = lp[1] * m;
    uint32_t hh, ll;
    split2(x0 * c - x1 * sn, x1 * c + x0 * sn, hh, ll);
    long o = ((long)(b * nH + h) * Sx + s) * 32 + i;
    qh[o] = hh; ql[o] = ll;
}

__global__ void k_sym(float* __restrict__ scg)
{
    int tj = blockIdx.x, ti = blockIdx.y, z = blockIdx.z;
    if (ti < tj) return;
    __shared__ float s[32][33];
    float* m = scg + (long)z * SSx;
    int tx = threadIdx.x;
    for (int a = threadIdx.y; a < 32; a += 8)
        s[a][tx] = m[(long)(tj * 32 + a) * Sx + ti * 32 + tx];
    __syncthreads();
    for (int a = threadIdx.y; a < 32; a += 8) {
        int i = ti * 32 + a, j = tj * 32 + tx;
        if (ti > tj || tx < a) m[(long)i * Sx + j] = s[tx][a];
    }
}

__global__ void k_adj(const float* __restrict__ scg,
                      uint32_t* __restrict__ adjh, uint32_t* __restrict__ adjl)
{
    int i = blockIdx.x % Sx;
    long bh = blockIdx.x / Sx;
    const float* row = scg + bh * SSx + (long)i * Sx;
    int t = threadIdx.x, lane = t & 31, w = t >> 5;
    float2 v = *(const float2*)&row[2 * t];
    __shared__ float red[6], red2[6];
    float m = fmaxf(v.x, v.y);
#pragma unroll
    for (int o = 16; o > 0; o >>= 1) m = fmaxf(m, __shfl_xor_sync(~0u, m, o));
    if (lane == 0) red[w] = m;
    __syncthreads();
    m = fmaxf(fmaxf(fmaxf(red[0], red[1]), fmaxf(red[2], red[3])), fmaxf(red[4], red[5]));
    float e0 = expf(v.x - m), e1 = expf(v.y - m), s = e0 + e1;
#pragma unroll
    for (int o = 16; o > 0; o >>= 1) s += __shfl_xor_sync(~0u, s, o);
    if (lane == 0) red2[w] = s;
    __syncthreads();
    s = red2[0] + red2[1] + red2[2] + red2[3] + red2[4] + red2[5];
    float is = 1.f / s;
    uint32_t hh, ll;
    split2((v.x != 0.f) ? e0 * is : 0.f, (v.y != 0.f) ? e1 * is : 0.f, hh, ll);
    long o = (bh * Sx + i) * 192 + t;
    adjh[o] = hh; adjl[o] = ll;
}

__global__ void k_ln(const float* __restrict__ agg, uint32_t* __restrict__ fh,
                     uint32_t* __restrict__ fl)
{
    long row = blockIdx.x;
    int t = threadIdx.x, lane = t & 31, w = t >> 5;
    float2 xv = *(const float2*)&agg[row * Hx + 2 * t];
    float v0 = fmaxf(xv.x, 0.f) * (1.f / 9.f);
    float v1 = fmaxf(xv.y, 0.f) * (1.f / 9.f);
    __shared__ float red[12], red2[12];
    float s = v0 + v1;
#pragma unroll
    for (int o = 16; o > 0; o >>= 1) s += __shfl_xor_sync(~0u, s, o);
    if (lane == 0) red[w] = s;
    __syncthreads();
    float tot = 0.f;
#pragma unroll
    for (int u = 0; u < 12; ++u) tot += red[u];
    float mean = tot * (1.f / 768.f);
    float d0 = v0 - mean, d1 = v1 - mean, s2 = d0 * d0 + d1 * d1;
#pragma unroll
    for (int o = 16; o > 0; o >>= 1) s2 += __shfl_xor_sync(~0u, s2, o);
    if (lane == 0) red2[w] = s2;
    __syncthreads();
    float tv = 0.f;
#pragma unroll
    for (int u = 0; u < 12; ++u) tv += red2[u];
    float rr = rsqrtf(tv * (1.f / 768.f) + 1e-5f);
    uint32_t hh, ll;
    split2(d0 * rr, d1 * rr, hh, ll);
    fh[row * 384 + t] = hh; fl[row * 384 + t] = ll;
}

__global__ void k_concat(const uint32_t* __restrict__ xh, const uint32_t* __restrict__ xl,
                         const uint32_t* __restrict__ fh, const uint32_t* __restrict__ fl,
                         uint32_t* __restrict__ ih, uint32_t* __restrict__ il)
{
    long idx = (long)blockIdx.x * blockDim.x + threadIdx.x;
    if (idx >= (long)Mx * 768) return;
    long row = idx / 768;
    int c = (int)(idx % 768);
    long src = row * 384 + (c < 384 ? c : c - 384);
    ih[idx] = (c < 384) ? xh[src] : fh[src];
    il[idx] = (c < 384) ? xl[src] : fl[src];
}

__global__ void k_pairs(const float* __restrict__ sp, const float* __restrict__ stp,
                        const float* __restrict__ sg, const float* __restrict__ stg,
                        float* __restrict__ out)
{
    int i = blockIdx.x, b = blockIdx.y, j = threadIdx.x;
    if (j < i) return;
    long p = (long)i * (2 * Sx - i + 1) / 2 + (j - i);
    long ss = SSx, ij = (long)i * Sx + j;
    const float* spb = sp + (long)b * ESSx * ss + ij;
    const float* sgb = sg + (long)b * HEADERx * ss + ij;
    float4 o0, o1, o2, o3;
    o0.x = spb[0];    o0.y = spb[ss];   o0.z = spb[2*ss]; o0.w = spb[3*ss];
    o1.x = spb[4*ss]; o1.y = spb[5*ss];
    o1.z = fmaxf(stp[(long)b*ss + ij], 0.f);
    o1.w = sgb[0];
    o2.x = sgb[ss];   o2.y = sgb[2*ss]; o2.z = sgb[3*ss]; o2.w = sgb[4*ss];
    o3.x = sgb[5*ss]; o3.y = sgb[6*ss]; o3.z = sgb[7*ss];
    o3.w = fmaxf(stg[(long)b*ss + ij], 0.f);
    float4* op = (float4*)(out + ((long)b * Px + p) * 16);
    op[0] = o0; op[1] = o1; op[2] = o2; op[3] = o3;
}

#define SYM(p, s) cudaGetSymbolAddress((void**)&p, s)

static void gsplit(const float* src, uint32_t* h, uint32_t* l, long elems) {
    long np = elems / 2;
    k_split<<<(int)((np + 255) / 256), 256>>>(src, h, l, np);
}
static void gemm(const uint32_t* Ah, const uint32_t* Al, long az, int lda,
                 const uint32_t* Wh, const uint32_t* Wl, long wz, int ldw,
                 const float* bias, int bz,
                 float* C, uint32_t* Ch, uint32_t* Cl, long cz, int ldc,
                 int M, int N, int KP, int flags, float scale, int Z)
{
    dim3 grid((N + 127) / 128, M / 128, Z);
    k_mma<<<grid, 256>>>(Ah, Al, az, lda, Wh, Wl, wz, ldw, bias, bz,
                         C, Ch, Cl, cz, ldc, N, KP, flags, scale);
}

extern "C" void kernel_launch(void* const* d_in, const int* in_sizes, int n_in,
                              void* d_out, int out_size)
{
    const float* x      = (const float*)d_in[0];
    const float* amask  = (const float*)d_in[1];
    const float* w1 = (const float*)d_in[2];   const float* b1 = (const float*)d_in[3];
    const float* w2 = (const float*)d_in[4];   const float* b2 = (const float*)d_in[5];
    const float* w3 = (const float*)d_in[6];   const float* b3 = (const float*)d_in[7];
    const float* w5 = (const float*)d_in[8];   const float* b5 = (const float*)d_in[9];
    const float* w4 = (const float*)d_in[10];  const float* b4 = (const float*)d_in[11];
    const float* w6 = (const float*)d_in[12];  const float* b6 = (const float*)d_in[13];
    const float* rgat_w = (const float*)d_in[14];
    const float* w7 = (const float*)d_in[15];  const float* b7 = (const float*)d_in[16];
    const float* w8 = (const float*)d_in[17];  const float* b8 = (const float*)d_in[18];
    const float* w9 = (const float*)d_in[19];  const float* b9 = (const float*)d_in[20];
    const float* w11 = (const float*)d_in[21]; const float* b11 = (const float*)d_in[22];
    const float* w10 = (const float*)d_in[23]; const float* b10 = (const float*)d_in[24];
    const float* w12 = (const float*)d_in[25]; const float* b12 = (const float*)d_in[26];
    float* out = (float*)d_out;

    float *lin, *lin2, *scg, *stg, *stp, *sp, *agg;
    SYM(lin, g_lin); SYM(lin2, g_lin2); SYM(scg, g_scg); SYM(stg, g_stg);
    SYM(stp, g_stp); SYM(sp, g_sp); SYM(agg, g_agg);
    uint32_t *xh,*xl,*hidh,*hidl,*tsqh,*tsql,*tskh,*tskl,*tqh,*tql,*tkh,*tkl;
    uint32_t *qgh,*qgl,*kgh,*kgl,*qph,*qpl,*kph,*kpl,*adjh,*adjl,*hrh,*hrl;
    uint32_t *feath,*featl,*inph,*inpl;
    uint32_t *wAh,*wAl,*wCh,*wCl,*wEh,*wEl,*wrh,*wrl,*wBh,*wBl,*wDh,*wDl,*wFh,*wFl;
    float *bA,*bC,*bE,*bB,*bD,*bF;
    SYM(xh,g_xh); SYM(xl,g_xl); SYM(hidh,g_hidh); SYM(hidl,g_hidl);
    SYM(tsqh,g_tsqh); SYM(tsql,g_tsql); SYM(tskh,g_tskh); SYM(tskl,g_tskl);
    SYM(tqh,g_tqh); SYM(tql,g_tql); SYM(tkh,g_tkh); SYM(tkl,g_tkl);
    SYM(qgh,g_qgh); SYM(qgl,g_qgl); SYM(kgh,g_kgh); SYM(kgl,g_kgl);
    SYM(qph,g_qph); SYM(qpl,g_qpl); SYM(kph,g_kph); SYM(kpl,g_kpl);
    SYM(adjh,g_adjh); SYM(adjl,g_adjl); SYM(hrh,g_hrh); SYM(hrl,g_hrl);
    SYM(feath,g_feath); SYM(featl,g_featl); SYM(inph,g_inph); SYM(inpl,g_inpl);
    SYM(wAh,g_wAh); SYM(wAl,g_wAl); SYM(wCh,g_wCh); SYM(wCl,g_wCl);
    SYM(wEh,g_wEh); SYM(wEl,g_wEl); SYM(wrh,g_wrh); SYM(wrl,g_wrl);
    SYM(wBh,g_wBh); SYM(wBl,g_wBl); SYM(wDh,g_wDh); SYM(wDl,g_wDl);
    SYM(wFh,g_wFh); SYM(wFl,g_wFl);
    SYM(bA,g_bA); SYM(bC,g_bC); SYM(bE,g_bE); SYM(bB,g_bB); SYM(bD,g_bD); SYM(bF,g_bF);

    const float inv = 0.125f;
    const long qs = (long)Sx * 32;

    k_init_rope<<<48, 256>>>();
    gsplit(x, xh, xl, (long)Mx * 768);
    gsplit(rgat_w, wrh, wrl, (long)2 * 9 * 768 * 768);
    gemm(wrh, wrl, (long)768 * 384, 384, xh, xl, 0, 384, 0, 0,
         0, hrh, hrl, (long)768 * 3072, 3072, Hx, Mx, 384, 6, 1.f, 5);
    gemm(wrh + (long)5 * 768 * 384, wrl + (long)5 * 768 * 384, (long)768 * 384, 384,
         xh, xl, 0, 384, 0, 0,
         0, hrh + (long)5 * 768 * 3072, hrl + (long)5 * 768 * 3072,
         (long)768 * 3072, 3072, Hx, Mx, 384, 6, 1.f, 4);

    gsplit(w1, wAh, wAl, 64 * 768);
    gsplit(w2, wAh + 64 * 384, wAl + 64 * 384, 64 * 768);
    gsplit(w3, wCh, wCl, 672 * 768);
    gsplit(w4, wCh + 672 * 384, wCl + 672 * 384, 672 * 768);
    gsplit(w5, wEh, wEl, 576 * 672);
    gsplit(w6, wEh + 576 * 336, wEl + 576 * 336, 576 * 672);
    gsplit(w7, wBh, wBl, 64 * 1536);
    gsplit(w8, wBh + 64 * 768, wBl + 64 * 768, 64 * 1536);
    gsplit(w9, wDh, wDl, 960 * 1536);
    gsplit(w10, wDh + 960 * 768, wDl + 960 * 768, 960 * 1536);
    gsplit(w11, wFh, wFl, 384 * 960);
    gsplit(w12, wFh + 384 * 480, wFl + 384 * 480, 384 * 960);
    cudaMemcpyAsync(bA, b1, 64*4, cudaMemcpyDeviceToDevice);
    cudaMemcpyAsync(bA+64, b2, 64*4, cudaMemcpyDeviceToDevice);
    cudaMemcpyAsync(bC, b3, 672*4, cudaMemcpyDeviceToDevice);
    cudaMemcpyAsync(bC+672, b4, 672*4, cudaMemcpyDeviceToDevice);
    cudaMemcpyAsync(bE, b5, 576*4, cudaMemcpyDeviceToDevice);
    cudaMemcpyAsync(bE+576, b6, 576*4, cudaMemcpyDeviceToDevice);
    cudaMemcpyAsync(bB, b7, 64*4, cudaMemcpyDeviceToDevice);
    cudaMemcpyAsync(bB+64, b8, 64*4, cudaMemcpyDeviceToDevice);
    cudaMemcpyAsync(bD, b9, 960*4, cudaMemcpyDeviceToDevice);
    cudaMemcpyAsync(bD+960, b10, 960*4, cudaMemcpyDeviceToDevice);
    cudaMemcpyAsync(bF, b11, 384*4, cudaMemcpyDeviceToDevice);
    cudaMemcpyAsync(bF+384, b12, 384*4, cudaMemcpyDeviceToDevice);

    gemm(xh, xl, 0, 384, wAh, wAl, 0, 384, bA, 0, lin, 0, 0, 0, 128,
         Mx, 128, 384, 0, 1.f, 1);
    k_rope<<<Mx, 32>>>(lin, amask, tsqh, tsql, 1, 128, 0);
    k_rope<<<Mx, 32>>>(lin, amask, tskh, tskl, 1, 128, 64);
    gemm(tsqh, tsql, qs, 32, tskh, tskl, qs, 32, 0, 0, stg, 0, 0, SSx, Sx,
         Sx, Sx, 32, 0, inv, Bx);

    gemm(xh, xl, 0, 384, wCh, wCl, 0, 384, bC, 0, 0, hidh, hidl, 0, 672,
         Mx, 1344, 384, 3, 1.f, 1);
    gemm(hidh, hidl, 336, 672, wEh, wEl, (long)576 * 336, 336, bE, 576,
         lin2, 0, 0, (long)Mx * 576, 576, Mx, 576, 336, 0, 1.f, 2);
    k_rope<<<Mx, 288>>>(lin2, amask, qgh, qgl, 9, 576, 0);
    k_rope<<<Mx, 288>>>(lin2 + (long)Mx * 576, amask, kgh, kgl, 9, 576, 0);
    gemm(qgh, qgl, qs, 32, kgh, kgl, qs, 32, 0, 0, scg, 0, 0, SSx, Sx,
         Sx, Sx, 32, 0, inv, Bx * HEADERx);
    k_sym<<<dim3(12, 12, Bx * HEADERx), dim3(32, 8)>>>(scg);
    k_adj<<<Bx * HEADERx * Sx, 192>>>(scg, adjh, adjl);

    k_agg<<<dim3(12, 3, Bx), 256>>>(adjh, adjl, hrh, agg);
    k_ln<<<Mx, 384>>>(agg, feath, featl);
    gemm(wrh + (long)9 * 768 * 384, wrl + (long)9 * 768 * 384, (long)768 * 384, 384,
         feath, featl, 0, 384, 0, 0, 0, hrh, hrl, (long)768 * 3072, 3072,
         Hx, Mx, 384, 6, 1.f, HEADERx);
    k_agg<<<dim3(12, 3, Bx), 256>>>(adjh, adjl, hrh, agg);
    k_ln<<<Mx, 384>>>(agg, feath, featl);

    k_concat<<<(int)(((long)Mx * 768 + 255) / 256), 256>>>(xh, xl, feath, featl, inph, inpl);

    gemm(inph, inpl, 0, 768, wBh, wBl, 0, 768, bB, 0, lin, 0, 0, 0, 128,
         Mx, 128, 768, 0, 1.f, 1);
    k_rope<<<Mx, 32>>>(lin, amask, tqh, tql, 1, 128, 0);
    k_rope<<<Mx, 32>>>(lin, amask, tkh, tkl, 1, 128, 64);
    gemm(tqh, tql, qs, 32, tkh, tkl, qs, 32, 0, 0, stp, 0, 0, SSx, Sx,
         Sx, Sx, 32, 0, inv, Bx);

    gemm(inph, inpl, 0, 768, wDh, wDl, 0, 768, bD, 0, 0, hidh, hidl, 0, 960,
         Mx, 1920, 768, 3, 1.f, 1);
    gemm(hidh, hidl, 480, 960, wFh, wFl, (long)384 * 480, 480, bF, 384,
         lin2, 0, 0, (long)Mx * 384, 384, Mx, 384, 480, 0, 1.f, 2);
    k_rope<<<Mx, 192>>>(lin2, amask, qph, qpl, 6, 384, 0);
    k_rope<<<Mx, 192>>>(lin2 + (long)Mx * 384, amask, kph, kpl, 6, 384, 0);
    gemm(qph, qpl, qs, 32, kph, kpl, qs, 32, 0, 0, sp, 0, 0, SSx, Sx,
         Sx, Sx, 32, 0, inv, Bx * ESSx);

    k_pairs<<<dim3(Sx, Bx), Sx>>>(sp, stp, scg, stg, out);
}